// round 12
// baseline (speedup 1.0000x reference)
#include <cuda_runtime.h>
#include <cuda_bf16.h>
#include <cstdint>

#define SEQL 2048
#define DH 64
#define BQ 128
#define BK 128
#define NT 16
#define NTHR 512

// smem byte offsets
#define QH 0
#define QL 18432
#define KH 36864
#define KL 55296
#define PH 36864
#define PL 71680
#define VHO 106496
#define VLO 123904
#define MS 141312
#define RS 157696
#define FLG 158208
#define SMTOT 158240

static __device__ __forceinline__ float fexp8(float x) {  // exp(x/8), FMA-pipe, clamped
    float t = x * 0.18033688011112042f;
    t = fminf(fmaxf(t, -126.0f), 126.0f);
    float kf = t + 12582912.0f;
    float f = t - (kf - 12582912.0f);
    int ki = __float_as_int(kf) << 23;
    float p = 1.3333558146e-3f;
    p = fmaf(p, f, 9.6181291076e-3f);
    p = fmaf(p, f, 5.55041086648e-2f);
    p = fmaf(p, f, 2.402265069591e-1f);
    p = fmaf(p, f, 6.931471805599e-1f);
    p = fmaf(p, f, 1.0f);
    return __int_as_float(__float_as_int(p) + ki);
}

static __device__ __forceinline__ void split2(float a, float b, uint32_t& hi, uint32_t& lo) {
    __nv_bfloat16 ha = __float2bfloat16_rn(a), hb = __float2bfloat16_rn(b);
    hi = (uint32_t)__bfloat16_as_ushort(ha) | ((uint32_t)__bfloat16_as_ushort(hb) << 16);
    lo = (uint32_t)__bfloat16_as_ushort(__float2bfloat16_rn(a - __bfloat162float(ha))) |
         ((uint32_t)__bfloat16_as_ushort(__float2bfloat16_rn(b - __bfloat162float(hb))) << 16);
}

static __device__ __forceinline__ void mma16816(float* c, const uint32_t* a, uint32_t b0, uint32_t b1) {
    asm volatile(
        "mma.sync.aligned.m16n8k16.row.col.f32.bf16.bf16.f32 "
        "{%0,%1,%2,%3}, {%4,%5,%6,%7}, {%8,%9}, {%0,%1,%2,%3};"
        : "+f"(c[0]), "+f"(c[1]), "+f"(c[2]), "+f"(c[3])
        : "r"(a[0]), "r"(a[1]), "r"(a[2]), "r"(a[3]), "r"(b0), "r"(b1));
}

// fp32 [128][64] gmem -> hi/lo bf16 smem, row stride 144B
static __device__ __forceinline__ void stage64(char* sm, int oh, int ol, const float* g, int tid) {
    for (int i = tid; i < 2048; i += NTHR) {
        int r = i >> 4, c = (i & 15) * 4;
        float4 x = __ldg((const float4*)(g + r * 64 + c));
        uint32_t h0, l0, h1, l1;
        split2(x.x, x.y, h0, l0); split2(x.z, x.w, h1, l1);
        *(uint2*)(sm + oh + r * 144 + c * 2) = make_uint2(h0, h1);
        *(uint2*)(sm + ol + r * 144 + c * 2) = make_uint2(l0, l1);
    }
}

static __device__ __forceinline__ void stage_mask(char* sm, const unsigned char* mg8,
                                                  const uint32_t* mg32, int t, int tid) {
    if (*(const int*)(sm + FLG)) {
        for (int i = tid; i < 4096; i += NTHR) {
            int r = i >> 5, c4 = (i & 31) * 4;
            uint4 wv = __ldg((const uint4*)(mg32 + (size_t)r * SEQL + t * BK + c4));
            *(uchar4*)(sm + MS + r * 128 + c4) =
                make_uchar4(wv.x != 0, wv.y != 0, wv.z != 0, wv.w != 0);
        }
    } else {
        for (int i = tid; i < 1024; i += NTHR) {
            int r = i >> 3, c = (i & 7) * 16;
            *(uint4*)(sm + MS + r * 128 + c) =
                __ldg((const uint4*)(mg8 + (size_t)r * SEQL + t * BK + c));
        }
    }
}

// QK MMA: acc[2][4][4]; warp tile rows wm*32+mf*16, cols wn*32+nf*8
static __device__ __forceinline__ void qk_mma(char* sm, float (*acc)[4][4],
                                              int wm, int wn, int g, int t4) {
#pragma unroll
    for (int ks = 0; ks < 4; ++ks) {
        uint32_t ah[2][4], al[2][4];
#pragma unroll
        for (int mf = 0; mf < 2; ++mf) {
            int rb = (wm * 32 + mf * 16 + g) * 144 + ks * 32 + t4 * 4;
            ah[mf][0] = *(uint32_t*)(sm + QH + rb);
            ah[mf][1] = *(uint32_t*)(sm + QH + rb + 8 * 144);
            ah[mf][2] = *(uint32_t*)(sm + QH + rb + 16);
            ah[mf][3] = *(uint32_t*)(sm + QH + rb + 8 * 144 + 16);
            al[mf][0] = *(uint32_t*)(sm + QL + rb);
            al[mf][1] = *(uint32_t*)(sm + QL + rb + 8 * 144);
            al[mf][2] = *(uint32_t*)(sm + QL + rb + 16);
            al[mf][3] = *(uint32_t*)(sm + QL + rb + 8 * 144 + 16);
        }
#pragma unroll
        for (int nf = 0; nf < 4; ++nf) {
            int cb = (wn * 32 + nf * 8 + g) * 144 + ks * 32 + t4 * 4;
            uint32_t bh0 = *(uint32_t*)(sm + KH + cb), bh1 = *(uint32_t*)(sm + KH + cb + 16);
            uint32_t bl0 = *(uint32_t*)(sm + KL + cb), bl1 = *(uint32_t*)(sm + KL + cb + 16);
#pragma unroll
            for (int mf = 0; mf < 2; ++mf) {
                mma16816(acc[mf][nf], ah[mf], bh0, bh1);
                mma16816(acc[mf][nf], ah[mf], bl0, bl1);
                mma16816(acc[mf][nf], al[mf], bh0, bh1);
            }
        }
    }
}

__global__ void __launch_bounds__(NTHR, 1)
sdpa_fused(const float* __restrict__ q, const float* __restrict__ k,
           const float* __restrict__ v, const unsigned char* __restrict__ mask,
           float* __restrict__ ctx, float* __restrict__ attn) {
    extern __shared__ char sm[];
    const int tid = threadIdx.x, lane = tid & 31, w = tid >> 5;
    const int g = lane >> 2, t4 = lane & 3, wm = w >> 2, wn = w & 3;
    const int qt = blockIdx.x, bh = blockIdx.y, b = bh >> 4, qb = qt * BQ;
    const float* qg = q + ((size_t)bh * SEQL + qb) * DH;
    const float* kg = k + (size_t)bh * SEQL * DH;
    const float* vg = v + (size_t)bh * SEQL * DH;
    const unsigned char* mg8 = mask + ((size_t)b * SEQL + qb) * SEQL;
    const uint32_t* mg32 = (const uint32_t*)mask + ((size_t)b * SEQL + qb) * SEQL;
    float* ag = attn + ((size_t)bh * SEQL + qb) * SEQL;
    float* rs = (float*)(sm + RS);
    if (tid < 128) rs[tid] = 0.f;
    if (tid == 0) {  // mask dtype probe
        const uint32_t* mw = (const uint32_t*)mask;
        uint32_t big = 0;
        for (int i = 0; i < 16; ++i) big |= (__ldg(mw + i) > 1u) ? 1u : 0u;
        *(int*)(sm + FLG) = big ? 0 : 1;
    }
    stage64(sm, QH, QL, qg, tid);

    float rsum[4] = {0.f, 0.f, 0.f, 0.f};

    // ---------------- PASS 1: row sums only ----------------
    for (int t = 0; t < NT; ++t) {
        __syncthreads();
        stage64(sm, KH, KL, kg + (size_t)t * BK * DH, tid);
        stage_mask(sm, mg8, mg32, t, tid);
        __syncthreads();
        float acc[2][4][4];
#pragma unroll
        for (int mf = 0; mf < 2; ++mf)
#pragma unroll
            for (int nf = 0; nf < 4; ++nf)
#pragma unroll
                for (int e = 0; e < 4; ++e) acc[mf][nf][e] = 0.f;
        qk_mma(sm, acc, wm, wn, g, t4);
#pragma unroll
        for (int mf = 0; mf < 2; ++mf)
#pragma unroll
            for (int nf = 0; nf < 4; ++nf) {
                int r0 = wm * 32 + mf * 16 + g, c0 = wn * 32 + nf * 8 + t4 * 2;
                unsigned m01 = *(unsigned short*)(sm + MS + r0 * 128 + c0);
                unsigned m23 = *(unsigned short*)(sm + MS + (r0 + 8) * 128 + c0);
                float e0 = (m01 & 0xffu) ? fexp8(acc[mf][nf][0]) : 1.0f;
                float e1 = (m01 >> 8)    ? fexp8(acc[mf][nf][1]) : 1.0f;
                float e2 = (m23 & 0xffu) ? fexp8(acc[mf][nf][2]) : 1.0f;
                float e3 = (m23 >> 8)    ? fexp8(acc[mf][nf][3]) : 1.0f;
                rsum[mf * 2] += e0 + e1;
                rsum[mf * 2 + 1] += e2 + e3;
            }
    }
#pragma unroll
    for (int i = 0; i < 4; ++i) {
        rsum[i] += __shfl_xor_sync(~0u, rsum[i], 1);
        rsum[i] += __shfl_xor_sync(~0u, rsum[i], 2);
    }
    __syncthreads();
    if (t4 == 0) {
        atomicAdd(&rs[wm * 32 + g], rsum[0]);
        atomicAdd(&rs[wm * 32 + g + 8], rsum[1]);
        atomicAdd(&rs[wm * 32 + 16 + g], rsum[2]);
        atomicAdd(&rs[wm * 32 + 24 + g], rsum[3]);
    }
    __syncthreads();
    if (tid < 128) rs[tid] = 1.0f / fmaxf(rs[tid], 1e-30f);  // rs becomes inv

    float accC[2][2][4];
#pragma unroll
    for (int mf = 0; mf < 2; ++mf)
#pragma unroll
        for (int nf = 0; nf < 2; ++nf)
#pragma unroll
            for (int e = 0; e < 4; ++e) accC[mf][nf][e] = 0.f;

    // ---------------- PASS 2: recompute, write attention, PV ----------------
    for (int t = 0; t < NT; ++t) {
        __syncthreads();   // prior PV reads done before restaging K over P
        stage64(sm, KH, KL, kg + (size_t)t * BK * DH, tid);
        stage_mask(sm, mg8, mg32, t, tid);
        // V transpose staging: conflict-free 32-bit stores, key pairs
        for (int i = tid; i < 1024; i += NTHR) {
            int kp = i & 63, dm = i >> 6;
            const float* vb = vg + (size_t)(t * BK + 2 * kp) * DH + dm * 4;
            float4 xa = __ldg((const float4*)vb);
            float4 xb = __ldg((const float4*)(vb + DH));
            float fa[4] = {xa.x, xa.y, xa.z, xa.w}, fb[4] = {xb.x, xb.y, xb.z, xb.w};
#pragma unroll
            for (int j = 0; j < 4; ++j) {
                uint32_t hi, lo;
                split2(fa[j], fb[j], hi, lo);  // key 2kp low half, 2kp+1 high half — but split2 packs (a,b)
                *(uint32_t*)(sm + VHO + (dm * 4 + j) * 272 + kp * 4) = hi;
                *(uint32_t*)(sm + VLO + (dm * 4 + j) * 272 + kp * 4) = lo;
            }
        }
        __syncthreads();
        float acc[2][4][4];
#pragma unroll
        for (int mf = 0; mf < 2; ++mf)
#pragma unroll
            for (int nf = 0; nf < 4; ++nf)
#pragma unroll
                for (int e = 0; e < 4; ++e) acc[mf][nf][e] = 0.f;
        qk_mma(sm, acc, wm, wn, g, t4);
        __syncthreads();   // all warps done reading K region before P overwrites it
#pragma unroll
        for (int mf = 0; mf < 2; ++mf) {
            int r0 = wm * 32 + mf * 16 + g;
            float il0 = rs[r0], il1 = rs[r0 + 8];
#pragma unroll
            for (int nf = 0; nf < 4; ++nf) {
                int c0 = wn * 32 + nf * 8 + t4 * 2;
                unsigned m01 = *(unsigned short*)(sm + MS + r0 * 128 + c0);
                unsigned m23 = *(unsigned short*)(sm + MS + (r0 + 8) * 128 + c0);
                float p0 = ((m01 & 0xffu) ? fexp8(acc[mf][nf][0]) : 1.0f) * il0;
                float p1 = ((m01 >> 8)    ? fexp8(acc[mf][nf][1]) : 1.0f) * il0;
                float p2 = ((m23 & 0xffu) ? fexp8(acc[mf][nf][2]) : 1.0f) * il1;
                float p3 = ((m23 >> 8)    ? fexp8(acc[mf][nf][3]) : 1.0f) * il1;
                float* d = ag + (size_t)r0 * SEQL + t * BK + c0;
                *(float2*)d = make_float2(p0, p1);
                *(float2*)(d + 8 * SEQL) = make_float2(p2, p3);
                uint32_t hi, lo;
                split2(p0, p1, hi, lo);
                *(uint32_t*)(sm + PH + r0 * 272 + c0 * 2) = hi;
                *(uint32_t*)(sm + PL + r0 * 272 + c0 * 2) = lo;
                split2(p2, p3, hi, lo);
                *(uint32_t*)(sm + PH + (r0 + 8) * 272 + c0 * 2) = hi;
                *(uint32_t*)(sm + PL + (r0 + 8) * 272 + c0 * 2) = lo;
            }
        }
        __syncthreads();   // P complete
#pragma unroll
        for (int ks = 0; ks < 8; ++ks) {
            uint32_t ah[2][4], al[2][4];
#pragma unroll
            for (int mf = 0; mf < 2; ++mf) {
                int rb = (wm * 32 + mf * 16 + g) * 272 + ks * 32 + t4 * 4;
                ah[mf][0] = *(uint32_t*)(sm + PH + rb);
                ah[mf][1] = *(uint32_t*)(sm + PH + rb + 8 * 272);
                ah[mf][2] = *(uint32_t*)(sm + PH + rb + 16);
                ah[mf][3] = *(uint32_t*)(sm + PH + rb + 8 * 272 + 16);
                al[mf][0] = *(uint32_t*)(sm + PL + rb);
                al[mf][1] = *(uint32_t*)(sm + PL + rb + 8 * 272);
                al[mf][2] = *(uint32_t*)(sm + PL + rb + 16);
                al[mf][3] = *(uint32_t*)(sm + PL + rb + 8 * 272 + 16);
            }
#pragma unroll
            for (int nf = 0; nf < 2; ++nf) {
                int db = (wn * 16 + nf * 8 + g) * 272 + ks * 32 + t4 * 4;
                uint32_t bh0 = *(uint32_t*)(sm + VHO + db), bh1 = *(uint32_t*)(sm + VHO + db + 16);
                uint32_t bl0 = *(uint32_t*)(sm + VLO + db), bl1 = *(uint32_t*)(sm + VLO + db + 16);
#pragma unroll
                for (int mf = 0; mf < 2; ++mf) {
                    mma16816(accC[mf][nf], ah[mf], bh0, bh1);
                    mma16816(accC[mf][nf], ah[mf], bl0, bl1);
                    mma16816(accC[mf][nf], al[mf], bh0, bh1);
                }
            }
        }
    }
#pragma unroll
    for (int mf = 0; mf < 2; ++mf)
#pragma unroll
        for (int nf = 0; nf < 2; ++nf) {
            int r0 = qb + wm * 32 + mf * 16 + g, d0 = wn * 16 + nf * 8 + t4 * 2;
            float* o = ctx + ((size_t)bh * SEQL + r0) * DH + d0;
            *(float2*)o = make_float2(accC[mf][nf][0], accC[mf][nf][1]);
            *(float2*)(o + 8 * DH) = make_float2(accC[mf][nf][2], accC[mf][nf][3]);
        }
}

extern "C" void kernel_launch(void* const* d_in, const int* in_sizes, int n_in,
                              void* d_out, int out_size) {
    const float* q = (const float*)d_in[0];
    const float* k = (const float*)d_in[1];
    const float* v = (const float*)d_in[2];
    const unsigned char* mask = (const unsigned char*)d_in[3];
    float* out = (float*)d_out;
    float* out_ctx = out;
    float* out_attn = out + (size_t)2 * 16 * SEQL * DH;

    cudaFuncSetAttribute(sdpa_fused, cudaFuncAttributeMaxDynamicSharedMemorySize, SMTOT);
    dim3 grid(SEQL / BQ, 32);
    sdpa_fused<<<grid, NTHR, SMTOT>>>(q, k, v, mask, out_ctx, out_attn);
}

// round 13
// speedup vs baseline: 1.6704x; 1.6704x over previous
#include <cuda_runtime.h>
#include <cuda_bf16.h>
#include <cstdint>

#define SEQL 2048
#define DH 64
#define BQ 128
#define BK 128
#define NT 16

__device__ float g_rowsum[2 * 16 * SEQL];

#define K1_QH 0
#define K1_QL 18432
#define K1_KH 36864
#define K1_KL 55296
#define K1_MS 73728
#define K1_RS 90112
#define K1_FLG 90624
#define K1_TOT 90656
#define K2_PH 0
#define K2_PL 34816
#define K2_VH 69632
#define K2_VL 87040
#define K2_INV 104448
#define K2_TOT 104960

static __device__ __forceinline__ float fexp8(float x) {  // exp(x/8), FMA-pipe, clamped
    float t = x * 0.18033688011112042f;
    t = fminf(fmaxf(t, -126.0f), 126.0f);
    float kf = t + 12582912.0f;
    float f = t - (kf - 12582912.0f);
    int ki = __float_as_int(kf) << 23;
    float p = 1.3333558146e-3f;
    p = fmaf(p, f, 9.6181291076e-3f);
    p = fmaf(p, f, 5.55041086648e-2f);
    p = fmaf(p, f, 2.402265069591e-1f);
    p = fmaf(p, f, 6.931471805599e-1f);
    p = fmaf(p, f, 1.0f);
    return __int_as_float(__float_as_int(p) + ki);
}

static __device__ __forceinline__ void split2(float a, float b, uint32_t& hi, uint32_t& lo) {
    __nv_bfloat16 ha = __float2bfloat16_rn(a), hb = __float2bfloat16_rn(b);
    hi = (uint32_t)__bfloat16_as_ushort(ha) | ((uint32_t)__bfloat16_as_ushort(hb) << 16);
    lo = (uint32_t)__bfloat16_as_ushort(__float2bfloat16_rn(a - __bfloat162float(ha))) |
         ((uint32_t)__bfloat16_as_ushort(__float2bfloat16_rn(b - __bfloat162float(hb))) << 16);
}

static __device__ __forceinline__ void mma16816(float* c, const uint32_t* a, uint32_t b0, uint32_t b1) {
    asm volatile(
        "mma.sync.aligned.m16n8k16.row.col.f32.bf16.bf16.f32 "
        "{%0,%1,%2,%3}, {%4,%5,%6,%7}, {%8,%9}, {%0,%1,%2,%3};"
        : "+f"(c[0]), "+f"(c[1]), "+f"(c[2]), "+f"(c[3])
        : "r"(a[0]), "r"(a[1]), "r"(a[2]), "r"(a[3]), "r"(b0), "r"(b1));
}

static __device__ __forceinline__ void stage64(char* sm, int oh, int ol, const float* g, int tid) {
    for (int i = tid; i < 2048; i += 256) {
        int r = i >> 4, c = (i & 15) * 4;
        float4 x = __ldg((const float4*)(g + r * 64 + c));
        uint32_t h0, l0, h1, l1;
        split2(x.x, x.y, h0, l0); split2(x.z, x.w, h1, l1);
        *(uint2*)(sm + oh + r * 144 + c * 2) = make_uint2(h0, h1);
        *(uint2*)(sm + ol + r * 144 + c * 2) = make_uint2(l0, l1);
    }
}

__global__ void __launch_bounds__(256, 2)
k1_qk_exp(const float* __restrict__ q, const float* __restrict__ k,
          const unsigned char* __restrict__ mask, float* __restrict__ attn) {
    extern __shared__ char sm[];
    const int tid = threadIdx.x, lane = tid & 31, w = tid >> 5;
    const int g = lane >> 2, t4 = lane & 3, wm = w >> 1, wn = w & 1;
    const int qt = blockIdx.x, bh = blockIdx.y, b = bh >> 4, qb = qt * BQ;
    const float* qg = q + ((size_t)bh * SEQL + qb) * DH;
    const float* kg = k + (size_t)bh * SEQL * DH;
    const unsigned char* mg8 = mask + ((size_t)b * SEQL + qb) * SEQL;
    const uint32_t* mg32 = (const uint32_t*)mask + ((size_t)b * SEQL + qb) * SEQL;
    float* ag = attn + ((size_t)bh * SEQL + qb) * SEQL;
    float* rs = (float*)(sm + K1_RS);
    if (tid < 128) rs[tid] = 0.f;
    if (tid == 0) {
        const uint32_t* mw = (const uint32_t*)mask;
        uint32_t big = 0;
        for (int i = 0; i < 16; ++i) big |= (__ldg(mw + i) > 1u) ? 1u : 0u;
        *(int*)(sm + K1_FLG) = big ? 0 : 1;
    }
    stage64(sm, K1_QH, K1_QL, qg, tid);

    float rsum[4] = {0.f, 0.f, 0.f, 0.f};

    for (int t = 0; t < NT; ++t) {
        __syncthreads();
        stage64(sm, K1_KH, K1_KL, kg + (size_t)t * BK * DH, tid);
        if (*(const int*)(sm + K1_FLG)) {
            for (int i = tid; i < 4096; i += 256) {
                int r = i >> 5, c4 = (i & 31) * 4;
                uint4 wv = __ldg((const uint4*)(mg32 + (size_t)r * SEQL + t * BK + c4));
                *(uchar4*)(sm + K1_MS + r * 128 + c4) =
                    make_uchar4(wv.x != 0, wv.y != 0, wv.z != 0, wv.w != 0);
            }
        } else {
            for (int i = tid; i < 1024; i += 256) {
                int r = i >> 3, c = (i & 7) * 16;
                *(uint4*)(sm + K1_MS + r * 128 + c) =
                    __ldg((const uint4*)(mg8 + (size_t)r * SEQL + t * BK + c));
            }
        }
        __syncthreads();

        float acc[2][8][4];
#pragma unroll
        for (int mf = 0; mf < 2; ++mf)
#pragma unroll
            for (int nf = 0; nf < 8; ++nf)
#pragma unroll
                for (int e = 0; e < 4; ++e) acc[mf][nf][e] = 0.f;

#pragma unroll
        for (int ks = 0; ks < 4; ++ks) {
            uint32_t ah[2][4], al[2][4];
#pragma unroll
            for (int mf = 0; mf < 2; ++mf) {
                int rb = (wm * 32 + mf * 16 + g) * 144 + ks * 32 + t4 * 4;
                ah[mf][0] = *(uint32_t*)(sm + K1_QH + rb);
                ah[mf][1] = *(uint32_t*)(sm + K1_QH + rb + 8 * 144);
                ah[mf][2] = *(uint32_t*)(sm + K1_QH + rb + 16);
                ah[mf][3] = *(uint32_t*)(sm + K1_QH + rb + 8 * 144 + 16);
                al[mf][0] = *(uint32_t*)(sm + K1_QL + rb);
                al[mf][1] = *(uint32_t*)(sm + K1_QL + rb + 8 * 144);
                al[mf][2] = *(uint32_t*)(sm + K1_QL + rb + 16);
                al[mf][3] = *(uint32_t*)(sm + K1_QL + rb + 8 * 144 + 16);
            }
#pragma unroll
            for (int nf = 0; nf < 8; ++nf) {
                int cb = (wn * 64 + nf * 8 + g) * 144 + ks * 32 + t4 * 4;
                uint32_t bh0 = *(uint32_t*)(sm + K1_KH + cb), bh1 = *(uint32_t*)(sm + K1_KH + cb + 16);
                uint32_t bl0 = *(uint32_t*)(sm + K1_KL + cb), bl1 = *(uint32_t*)(sm + K1_KL + cb + 16);
#pragma unroll
                for (int mf = 0; mf < 2; ++mf) {
                    mma16816(acc[mf][nf], ah[mf], bh0, bh1);
                    mma16816(acc[mf][nf], ah[mf], bl0, bl1);
                    mma16816(acc[mf][nf], al[mf], bh0, bh1);
                }
            }
        }

#pragma unroll
        for (int mf = 0; mf < 2; ++mf)
#pragma unroll
            for (int nf = 0; nf < 8; ++nf) {
                int r0 = wm * 32 + mf * 16 + g, c0 = wn * 64 + nf * 8 + t4 * 2;
                unsigned m01 = *(unsigned short*)(sm + K1_MS + r0 * 128 + c0);
                unsigned m23 = *(unsigned short*)(sm + K1_MS + (r0 + 8) * 128 + c0);
                float e0 = (m01 & 0xffu) ? fexp8(acc[mf][nf][0]) : 1.0f;
                float e1 = (m01 >> 8)    ? fexp8(acc[mf][nf][1]) : 1.0f;
                float e2 = (m23 & 0xffu) ? fexp8(acc[mf][nf][2]) : 1.0f;
                float e3 = (m23 >> 8)    ? fexp8(acc[mf][nf][3]) : 1.0f;
                rsum[mf * 2] += e0 + e1;
                rsum[mf * 2 + 1] += e2 + e3;
                float* d = ag + (size_t)r0 * SEQL + t * BK + c0;
                __stcs((float2*)d, make_float2(e0, e1));
                __stcs((float2*)(d + 8 * SEQL), make_float2(e2, e3));
            }
    }

#pragma unroll
    for (int i = 0; i < 4; ++i) {
        rsum[i] += __shfl_xor_sync(~0u, rsum[i], 1);
        rsum[i] += __shfl_xor_sync(~0u, rsum[i], 2);
    }
    if (t4 == 0) {
        atomicAdd(&rs[wm * 32 + g], rsum[0]);
        atomicAdd(&rs[wm * 32 + g + 8], rsum[1]);
        atomicAdd(&rs[wm * 32 + 16 + g], rsum[2]);
        atomicAdd(&rs[wm * 32 + 24 + g], rsum[3]);
    }
    __syncthreads();
    if (tid < 128) g_rowsum[(size_t)bh * SEQL + qb + tid] = rs[tid];
}

__global__ void __launch_bounds__(256, 2)
k2_norm_pv(const float* __restrict__ v, float* __restrict__ attn, float* __restrict__ ctx) {
    extern __shared__ char sm[];
    const int tid = threadIdx.x, lane = tid & 31, w = tid >> 5;
    const int g = lane >> 2, t4 = lane & 3, wm = w >> 1, wn = w & 1;
    const int qt = blockIdx.x, bh = blockIdx.y, qb = qt * BQ;
    float* ag = attn + ((size_t)bh * SEQL + qb) * SEQL;
    const float* vg = v + (size_t)bh * SEQL * DH;
    float* inv = (float*)(sm + K2_INV);
    if (tid < 128)
        inv[tid] = 1.0f / fmaxf(g_rowsum[(size_t)bh * SEQL + qb + tid], 1e-30f);

    float acc[2][4][4];
#pragma unroll
    for (int mf = 0; mf < 2; ++mf)
#pragma unroll
        for (int nf = 0; nf < 4; ++nf)
#pragma unroll
            for (int e = 0; e < 4; ++e) acc[mf][nf][e] = 0.f;

    for (int t = 0; t < NT; ++t) {
        __syncthreads();
        // normalize e -> attention (write .cs) + stage split P; batched loads (MLP=4)
#pragma unroll
        for (int ii = 0; ii < 16; ii += 4) {
            float4 e4[4];
            int rr[4], cc[4];
#pragma unroll
            for (int j = 0; j < 4; ++j) {
                int i = (ii + j) * 256 + tid;
                rr[j] = i >> 5; cc[j] = (i & 31) * 4;
                e4[j] = *(const float4*)(ag + (size_t)rr[j] * SEQL + t * BK + cc[j]);
            }
#pragma unroll
            for (int j = 0; j < 4; ++j) {
                float il = inv[rr[j]];
                float4 e = e4[j];
                e.x *= il; e.y *= il; e.z *= il; e.w *= il;
                __stcs((float4*)(ag + (size_t)rr[j] * SEQL + t * BK + cc[j]), e);
                uint32_t h0, l0, h1, l1;
                split2(e.x, e.y, h0, l0); split2(e.z, e.w, h1, l1);
                *(uint2*)(sm + K2_PH + rr[j] * 272 + cc[j] * 2) = make_uint2(h0, h1);
                *(uint2*)(sm + K2_PL + rr[j] * 272 + cc[j] * 2) = make_uint2(l0, l1);
            }
        }
        // V transpose staging: conflict-free 32-bit key-pair stores (proven in R11)
        for (int i = tid; i < 1024; i += 256) {
            int kp = i & 63, dm = i >> 6;
            const float* vb = vg + (size_t)(t * BK + 2 * kp) * DH + dm * 4;
            float4 xa = __ldg((const float4*)vb);
            float4 xb = __ldg((const float4*)(vb + DH));
            float fa[4] = {xa.x, xa.y, xa.z, xa.w}, fb[4] = {xb.x, xb.y, xb.z, xb.w};
#pragma unroll
            for (int j = 0; j < 4; ++j) {
                uint32_t hi, lo;
                split2(fa[j], fb[j], hi, lo);
                *(uint32_t*)(sm + K2_VH + (dm * 4 + j) * 272 + kp * 4) = hi;
                *(uint32_t*)(sm + K2_VL + (dm * 4 + j) * 272 + kp * 4) = lo;
            }
        }
        __syncthreads();

#pragma unroll
        for (int ks = 0; ks < 8; ++ks) {
            uint32_t ah[2][4], al[2][4];
#pragma unroll
            for (int mf = 0; mf < 2; ++mf) {
                int rb = (wm * 32 + mf * 16 + g) * 272 + ks * 32 + t4 * 4;
                ah[mf][0] = *(uint32_t*)(sm + K2_PH + rb);
                ah[mf][1] = *(uint32_t*)(sm + K2_PH + rb + 8 * 272);
                ah[mf][2] = *(uint32_t*)(sm + K2_PH + rb + 16);
                ah[mf][3] = *(uint32_t*)(sm + K2_PH + rb + 8 * 272 + 16);
                al[mf][0] = *(uint32_t*)(sm + K2_PL + rb);
                al[mf][1] = *(uint32_t*)(sm + K2_PL + rb + 8 * 272);
                al[mf][2] = *(uint32_t*)(sm + K2_PL + rb + 16);
                al[mf][3] = *(uint32_t*)(sm + K2_PL + rb + 8 * 272 + 16);
            }
#pragma unroll
            for (int nf = 0; nf < 4; ++nf) {
                int db = (wn * 32 + nf * 8 + g) * 272 + ks * 32 + t4 * 4;
                uint32_t bh0 = *(uint32_t*)(sm + K2_VH + db), bh1 = *(uint32_t*)(sm + K2_VH + db + 16);
                uint32_t bl0 = *(uint32_t*)(sm + K2_VL + db), bl1 = *(uint32_t*)(sm + K2_VL + db + 16);
#pragma unroll
                for (int mf = 0; mf < 2; ++mf) {
                    mma16816(acc[mf][nf], ah[mf], bh0, bh1);
                    mma16816(acc[mf][nf], ah[mf], bl0, bl1);
                    mma16816(acc[mf][nf], al[mf], bh0, bh1);
                }
            }
        }
    }
#pragma unroll
    for (int mf = 0; mf < 2; ++mf)
#pragma unroll
        for (int nf = 0; nf < 4; ++nf) {
            int r0 = qb + wm * 32 + mf * 16 + g, d0 = wn * 32 + nf * 8 + t4 * 2;
            float* o = ctx + ((size_t)bh * SEQL + r0) * DH + d0;
            *(float2*)o = make_float2(acc[mf][nf][0], acc[mf][nf][1]);
            *(float2*)(o + 8 * DH) = make_float2(acc[mf][nf][2], acc[mf][nf][3]);
        }
}

extern "C" void kernel_launch(void* const* d_in, const int* in_sizes, int n_in,
                              void* d_out, int out_size) {
    const float* q = (const float*)d_in[0];
    const float* k = (const float*)d_in[1];
    const float* v = (const float*)d_in[2];
    const unsigned char* mask = (const unsigned char*)d_in[3];
    float* out = (float*)d_out;
    float* out_ctx = out;
    float* out_attn = out + (size_t)2 * 16 * SEQL * DH;

    cudaFuncSetAttribute(k1_qk_exp, cudaFuncAttributeMaxDynamicSharedMemorySize, K1_TOT);
    cudaFuncSetAttribute(k2_norm_pv, cudaFuncAttributeMaxDynamicSharedMemorySize, K2_TOT);
    dim3 grid(SEQL / BQ, 32);
    k1_qk_exp<<<grid, 256, K1_TOT>>>(q, k, mask, out_attn);
    k2_norm_pv<<<grid, 256, K2_TOT>>>(v, out_attn, out_ctx);
}